// round 11
// baseline (speedup 1.0000x reference)
#include <cuda_runtime.h>
#include <cstdint>

#define NA     17064
#define KTOP   1000
#define NBINS  16384
#define CCAP   4096
#define NT     512
#define B      16
#define NCTA   128
#define FULL   0xffffffffu

typedef unsigned long long u64;

// ---------------- static device scratch ----------------
__device__ unsigned ghist[B][NBINS];      // zero-init; re-zeroed each pass
__device__ unsigned gcnt[B];
__device__ u64      gkey[B][CCAP];
__device__ unsigned grank[B][CCAP];       // zeroed in P1 each pass
__device__ float    gssc[B][KTOP];
__device__ unsigned gslab[B][KTOP];
__device__ unsigned gvbits[B][32];
__device__ float4   gsbox[B][KTOP];
__device__ float    gsx1[B][KTOP], gsy1[B][KTOP], gsx2[B][KTOP],
                    gsy2[B][KTOP], gsar[B][KTOP];
__device__ __align__(16) unsigned gmat[B][KTOP][32];
__device__ __align__(16) unsigned gdiag[B][1024];
__device__ unsigned gnzw[B][32];          // row-nonzero bitmap
__device__ unsigned gbarc[B][8];          // per-batch epoch barrier counters

// Exact sigmoid: float exp via double exp (correctly rounded to float =>
// matches faithful libm expf), then float add + div as XLA expands logistic.
__device__ __forceinline__ float sigx(float x) {
    float t = (float)exp(-(double)x);
    return __fdiv_rn(1.0f, __fadd_rn(1.0f, t));
}
// Fast approximate sigmoid — superset selection only.
__device__ __forceinline__ float siga(float x) {
    return __fdividef(1.0f, 1.0f + __expf(-x));
}
// per-batch barrier (8 CTAs), epoch-based, graph-replay safe
__device__ __forceinline__ void bbarrier(int b, int k) {
    __syncthreads();
    if (threadIdx.x == 0) {
        __threadfence();
        unsigned old   = atomicAdd(&gbarc[b][k], 1u);
        unsigned epoch = old >> 3;
        volatile unsigned* p = &gbarc[b][k];
        unsigned target = (epoch + 1u) << 3;
        while (*p < target) { }
        __threadfence();
    }
    __syncthreads();
}
// guarded warp suffix-sum (inclusive from high lanes)
__device__ __forceinline__ unsigned suffix_sum(unsigned v, int lane) {
#pragma unroll
    for (int o = 1; o < 32; o <<= 1) {
        unsigned t = __shfl_down_sync(FULL, v, o);
        if (lane + o < 32) v += t;
    }
    return v;
}

#define SMEM_TOTAL 33024    // max: rank keys 32KB; boxes 20KB; sdiag 4KB
extern __shared__ unsigned char smem_raw[];

__global__ void __launch_bounds__(NT, 1)
fcos_persist(const float* __restrict__ cls, const float* __restrict__ ctr,
             const float* __restrict__ reg, const float* __restrict__ coords,
             const float* __restrict__ pstr, float* __restrict__ out)
{
    const int cta  = blockIdx.x;
    const int b    = cta >> 3;
    const int r    = cta & 7;
    const int tid  = threadIdx.x;
    const int lane = tid & 31;
    const int wid  = tid >> 5;       // 0..15

    __shared__ unsigned chunk[512];
    __shared__ unsigned supr[16];
    __shared__ float redmax[16], redmin[16];
    __shared__ float s_mx, s_mn;
    __shared__ unsigned s_thr, srem[32];

    const float4* clsB = (const float4*)cls + (size_t)b * NA;
    const float*  ctrB = ctr + (size_t)b * NA;

    // ============ P1: zero grank slice + approx-score histogram =============
    if (r == 0 && tid == 0) gcnt[b] = 0;
    grank[b][r * 512 + tid] = 0u;
    for (int i0 = r * NT; i0 < NA; i0 += 8 * NT) {   // uniform trip per CTA
        int i = i0 + tid;
        if (i < NA) {
            float4 c = clsB[i];
            float m = fmaxf(fmaxf(c.x, c.y), fmaxf(c.z, c.w));  // sig monotone
            float score = __fsqrt_rn(siga(m) * siga(ctrB[i]));
            atomicAdd(&ghist[b][__float_as_uint(score) >> 16], 1u);
        }
    }
    bbarrier(b, 0);

    // ============ P2: threshold (warp scans, 32 bins/chunk) ==================
    { unsigned s = 0; int base = tid * 32;
#pragma unroll
      for (int q = 0; q < 32; ++q) s += ghist[b][base + q];
      chunk[tid] = s; }
    __syncthreads();
    { unsigned s = chunk[wid * 32 + lane];
#pragma unroll
      for (int o = 16; o; o >>= 1) s += __shfl_xor_sync(FULL, s, o);
      if (lane == 0) supr[wid] = s; }
    __syncthreads();
    if (wid == 0) {
        unsigned suf = suffix_sum((lane < 16) ? supr[lane] : 0u, lane);
        unsigned m1  = __ballot_sync(FULL, suf >= KTOP);
        int sblk     = 31 - __clz(m1);
        unsigned above = (sblk < 15) ? __shfl_sync(FULL, suf, sblk + 1) : 0u;
        unsigned cs  = suffix_sum(chunk[sblk * 32 + lane], lane);
        unsigned m2  = __ballot_sync(FULL, cs + above >= KTOP);
        int cc       = 31 - __clz(m2);
        unsigned above2 = above + ((cc < 31) ? __shfl_sync(FULL, cs, cc + 1) : 0u);
        int binbase  = (sblk * 32 + cc) * 32;
        unsigned bs  = suffix_sum(ghist[b][binbase + lane], lane);
        unsigned m3  = __ballot_sync(FULL, bs + above2 >= KTOP);
        int bb       = 31 - __clz(m3);
        if (lane == 0) {
            int T = binbase + bb;
            s_thr = (T > 0) ? (unsigned)(T - 1) : 0u;   // one-bin superset margin
        }
    }
    __syncthreads();
    const unsigned T = s_thr;

    // ============ P2b: fused compact + exact rescore (warp-agg atomic) ======
    for (int i0 = r * NT; i0 < NA; i0 += 8 * NT) {
        int i = i0 + tid;
        bool in = (i < NA);
        float4 c = make_float4(0.f, 0.f, 0.f, 0.f);
        float ctrv = 0.f;
        bool isc = false;
        if (in) {
            c = clsB[i];
            float m = fmaxf(fmaxf(c.x, c.y), fmaxf(c.z, c.w));
            ctrv = ctrB[i];
            float sa = __fsqrt_rn(siga(m) * siga(ctrv));
            isc = ((__float_as_uint(sa) >> 16) >= T);
        }
        unsigned bal = __ballot_sync(FULL, isc);
        if (bal) {
            int leader = __ffs(bal) - 1;
            unsigned base = 0;
            if (lane == leader) base = atomicAdd(&gcnt[b], __popc(bal));
            base = __shfl_sync(FULL, base, leader);
            if (isc) {
                unsigned p = base + __popc(bal & ((1u << lane) - 1u));
                if (p < CCAP) {
                    float xs0 = c.x, xs1 = c.y, xs2 = c.z, xs3 = c.w;
                    int im = 0; float mm = xs0;
                    if (xs1 > mm) { mm = xs1; im = 1; }
                    if (xs2 > mm) { mm = xs2; im = 2; }
                    if (xs3 > mm) { mm = xs3; im = 3; }
                    float sm = sigx(mm);                 // == max of 4 sigmoids
                    int lab = im;
                    if (im > 0) {                        // first-argmax tie guard
                        float lim = mm - 1e-4f;
                        if (xs0 > lim || (im > 1 && xs1 > lim) || (im > 2 && xs2 > lim)) {
                            if (xs0 > lim && sigx(xs0) == sm) lab = 0;
                            else if (im > 1 && xs1 > lim && sigx(xs1) == sm) lab = 1;
                            else if (im > 2 && xs2 > lim && sigx(xs2) == sm) lab = 2;
                        }
                    }
                    float sctr  = sigx(ctrv);
                    float score = __fsqrt_rn(__fmul_rn(sm, sctr));
                    gkey[b][p] = ((u64)__float_as_uint(score) << 32)
                               | ((u64)(0x7FFFu - (unsigned)i) << 4) | (u64)(lab + 1);
                }
            }
        }
    }
    bbarrier(b, 1);

    int C = (int)gcnt[b]; if (C > CCAP) C = CCAP;

    // ============ P3: brute-force rank (8 CTAs, O(C^2)/8 each) ==============
    {
        u64* skeys = (u64*)smem_raw;
        for (int i = tid; i < C; i += NT) skeys[i] = gkey[b][i];
        __syncthreads();
        int j0 = (r * C) >> 3, j1 = ((r + 1) * C) >> 3;
        for (int i = tid; i < C; i += NT) {
            u64 ki = skeys[i];
            unsigned cnt = 0;
#pragma unroll 4
            for (int j = j0; j < j1; ++j) cnt += (skeys[j] > ki) ? 1u : 0u;
            if (cnt) atomicAdd(&grank[b][i], cnt);
        }
    }
    bbarrier(b, 2);

    // ============ P4: r==0 gather-by-rank + boxes; r>0 zero hist/nz =========
    if (r == 0) {
        u64* skey = (u64*)smem_raw;             // KTOP u64
        for (int i = tid; i < C; i += NT) {
            unsigned rk = grank[b][i];
            if (rk < KTOP) skey[rk] = gkey[b][i];
        }
        __syncthreads();

        float bx1[2], by1[2], bx2[2], by2[2];
        int   blab[2]; bool bval[2];
        float vmax = -1000000000.0f, vmin = 1000000000.0f;
#pragma unroll
        for (int n = 0; n < 2; ++n) {
            int q = tid + n * NT;
            bval[n] = false; blab[n] = 0;
            bx1[n] = by1[n] = bx2[n] = by2[n] = 0.f;
            bool validf = false;
            if (q < KTOP) {
                u64 key = skey[q];
                float score = __uint_as_float((unsigned)(key >> 32));
                int label   = (int)(key & 0xFull);
                int idx = 0x7FFF - (int)((key >> 4) & 0x7FFFull);
                validf = (score >= 0.05f);

                float4 r4 = ((const float4*)reg)[(size_t)b * NA + idx];
                float2 xy = ((const float2*)coords)[idx];
                float  st = pstr[idx];
                float x1 = __fsub_rn(xy.x, __fmul_rn(r4.x, st));
                float y1 = __fsub_rn(xy.y, __fmul_rn(r4.y, st));
                float x2 = __fadd_rn(xy.x, __fmul_rn(r4.z, st));
                float y2 = __fadd_rn(xy.y, __fmul_rn(r4.w, st));
                x1 = fminf(fmaxf(x1, 0.0f), 1023.0f);
                y1 = fminf(fmaxf(y1, 0.0f), 799.0f);
                x2 = fminf(fmaxf(x2, 0.0f), 1023.0f);
                y2 = fminf(fmaxf(y2, 0.0f), 799.0f);

                gsbox[b][q] = make_float4(x1, y1, x2, y2);
                gssc[b][q]  = score;
                gslab[b][q] = (unsigned)label;
                bx1[n] = x1; by1[n] = y1; bx2[n] = x2; by2[n] = y2;
                blab[n] = label; bval[n] = validf;
                if (validf) {
                    vmax = fmaxf(vmax, fmaxf(fmaxf(x1, y1), fmaxf(x2, y2)));
                    vmin = fminf(vmin, fminf(fminf(x1, y1), fminf(x2, y2)));
                }
            }
            unsigned vb = __ballot_sync(FULL, validf);
            if (lane == 0) gvbits[b][wid + n * 16] = vb;
        }
#pragma unroll
        for (int o = 16; o; o >>= 1) {
            vmax = fmaxf(vmax, __shfl_xor_sync(FULL, vmax, o));
            vmin = fminf(vmin, __shfl_xor_sync(FULL, vmin, o));
        }
        if (lane == 0) { redmax[wid] = vmax; redmin[wid] = vmin; }
        __syncthreads();
        if (tid == 0) {
            float mx = redmax[0], mn = redmin[0];
            for (int w = 1; w < 16; ++w) { mx = fmaxf(mx, redmax[w]); mn = fminf(mn, redmin[w]); }
            s_mx = mx; s_mn = mn;
        }
        __syncthreads();
#pragma unroll
        for (int n = 0; n < 2; ++n) {
            int q = tid + n * NT;
            if (q < KTOP) {
                float off = __fmul_rn((float)blab[n], __fadd_rn(__fsub_rn(s_mx, s_mn), 1.0f));
                float a  = __fadd_rn(bx1[n], off), bb = __fadd_rn(by1[n], off);
                float cc = __fadd_rn(bx2[n], off), dd = __fadd_rn(by2[n], off);
                gsx1[b][q] = a;  gsy1[b][q] = bb;
                gsx2[b][q] = cc; gsy2[b][q] = dd;
                gsar[b][q] = __fmul_rn(__fsub_rn(cc, a), __fsub_rn(dd, bb));
            }
        }
    } else {
        int z0 = (r - 1) * 2341, z1 = (r == 7) ? NBINS : z0 + 2341;
        for (int i = z0 + tid; i < z1; i += NT) ghist[b][i] = 0;
        if (r == 1 && tid < 32) gnzw[b][tid] = 0u;
    }
    bbarrier(b, 3);

    // ============ P5: bit-matrix + diag + nz bitmap (all 8 CTAs) ============
    {
        float* sx1 = (float*)smem_raw;
        float* sy1 = sx1 + KTOP; float* sx2 = sy1 + KTOP;
        float* sy2 = sx2 + KTOP; float* sar = sy2 + KTOP;
        for (int j = tid; j < KTOP; j += NT) {
            sx1[j] = gsx1[b][j]; sy1[j] = gsy1[b][j];
            sx2[j] = gsx2[b][j]; sy2[j] = gsy2[b][j];
            sar[j] = gsar[b][j];
        }
        __syncthreads();

        for (int k = wid; k < 125; k += 16) {
            int i = r + 8 * k;                        // interleaved -> balanced
            float ax1 = sx1[i], ay1 = sy1[i], ax2 = sx2[i], ay2 = sy2[i], aa = sar[i];
            unsigned myword = 0;
            int jc0 = (i + 1) >> 5;
            for (int jc = jc0; jc < 32; ++jc) {       // uniform per warp
                int j = jc * 32 + lane;
                bool sup = false;
                if (j > i && j < KTOP) {
                    float ix1 = fmaxf(ax1, sx1[j]);
                    float iy1 = fmaxf(ay1, sy1[j]);
                    float ix2 = fminf(ax2, sx2[j]);
                    float iy2 = fminf(ay2, sy2[j]);
                    float iw  = fmaxf(__fsub_rn(ix2, ix1), 0.0f);
                    float ih  = fmaxf(__fsub_rn(iy2, iy1), 0.0f);
                    float inter = __fmul_rn(iw, ih);
                    float uni = fmaxf(__fsub_rn(__fadd_rn(aa, sar[j]), inter), 1e-9f);
                    sup = __fdiv_rn(inter, uni) > 0.5f;
                }
                unsigned wbits = __ballot_sync(FULL, sup);
                if (lane == jc) myword = wbits;
            }
            gmat[b][i][lane] = myword;
            if (lane == (i >> 5)) gdiag[b][i] = myword;
            unsigned any = __ballot_sync(FULL, myword != 0u);
            if (lane == 0 && any) atomicOr(&gnzw[b][i >> 5], 1u << (i & 31));
        }
    }
    bbarrier(b, 4);

    // ============ P6: sparse block-serial NMS + outputs (r==0) ==============
    if (r != 0) return;
    {
        unsigned* sdiag = (unsigned*)smem_raw;        // 1024 u32
        for (int i = tid; i < 1024; i += NT)
            sdiag[i] = (i < KTOP) ? gdiag[b][i] : 0u;
        __syncthreads();

        if (wid == 0) {
            unsigned removed = ~gvbits[b][lane];      // lane owns [32l, 32l+32)
            unsigned nz = gnzw[b][lane];
            for (int bk = 0; bk < 32; ++bk) {
                unsigned curw = __shfl_sync(FULL, removed, bk);
                unsigned kept = 0;
                if (lane == 0) {
                    const uint4* dg = (const uint4*)(sdiag + bk * 32);
                    uint4 v0 = dg[0], v1 = dg[1], v2 = dg[2], v3 = dg[3];
                    uint4 v4 = dg[4], v5 = dg[5], v6 = dg[6], v7 = dg[7];
                    unsigned anyd = (v0.x|v0.y|v0.z|v0.w)|(v1.x|v1.y|v1.z|v1.w)
                                  | (v2.x|v2.y|v2.z|v2.w)|(v3.x|v3.y|v3.z|v3.w)
                                  | (v4.x|v4.y|v4.z|v4.w)|(v5.x|v5.y|v5.z|v5.w)
                                  | (v6.x|v6.y|v6.z|v6.w)|(v7.x|v7.y|v7.z|v7.w);
                    if (anyd == 0u) {
                        kept = ~curw;
                    } else {
                        unsigned rem = curw;
                        const uint4 vv[8] = {v0,v1,v2,v3,v4,v5,v6,v7};
#pragma unroll
                        for (int q = 0; q < 8; ++q) {
                            int j0 = q * 4;
                            if (!((rem >> (j0+0)) & 1u)) { kept |= 1u << (j0+0); rem |= vv[q].x; }
                            if (!((rem >> (j0+1)) & 1u)) { kept |= 1u << (j0+1); rem |= vv[q].y; }
                            if (!((rem >> (j0+2)) & 1u)) { kept |= 1u << (j0+2); rem |= vv[q].z; }
                            if (!((rem >> (j0+3)) & 1u)) { kept |= 1u << (j0+3); rem |= vv[q].w; }
                        }
                    }
                }
                kept = __shfl_sync(FULL, kept, 0);
                unsigned todo = kept & __shfl_sync(FULL, nz, bk);
                while (todo) {                        // warp-uniform
                    int j = __ffs(todo) - 1; todo &= todo - 1;
                    removed |= gmat[b][bk * 32 + j][lane];
                }
            }
            srem[lane] = removed;
        }
        __syncthreads();

        for (int q = tid; q < KTOP; q += NT) {
            bool k = ((srem[q >> 5] >> (q & 31)) & 1u) == 0u;
            float so = k ? gssc[b][q] : 0.0f;
            float lo = k ? (float)gslab[b][q] : 0.0f;
            float4 bx = gsbox[b][q];
            if (!k) bx = make_float4(0.f, 0.f, 0.f, 0.f);
            out[(size_t)b * KTOP + q] = so;
            out[(size_t)(B * KTOP) + (size_t)b * KTOP + q] = lo;
            size_t base = (size_t)(2 * B * KTOP) + ((size_t)b * KTOP + q) * 4;
            out[base + 0] = bx.x; out[base + 1] = bx.y;
            out[base + 2] = bx.z; out[base + 3] = bx.w;
        }
    }
}

extern "C" void kernel_launch(void* const* d_in, const int* in_sizes, int n_in,
                              void* d_out, int out_size) {
    (void)in_sizes; (void)n_in; (void)out_size;
    static bool attr_done = false;
    if (!attr_done) {
        cudaFuncSetAttribute(fcos_persist, cudaFuncAttributeMaxDynamicSharedMemorySize,
                             SMEM_TOTAL);
        attr_done = true;
    }
    fcos_persist<<<NCTA, NT, SMEM_TOTAL>>>(
        (const float*)d_in[0], (const float*)d_in[1], (const float*)d_in[2],
        (const float*)d_in[3], (const float*)d_in[4], (float*)d_out);
}

// round 13
// speedup vs baseline: 1.4647x; 1.4647x over previous
#include <cuda_runtime.h>
#include <cstdint>

#define NA     17064
#define KTOP   1000
#define NBINS  16384
#define CCAP   4096
#define NT     1024
#define B      16
#define NCTA   128
#define ROWS   1104          // padded flat rows (32-aligned class bases)
#define FULL   0xffffffffu

typedef unsigned long long u64;

// ---------------- static device scratch ----------------
__device__ unsigned ghist[B][NBINS];      // zero-init; re-zeroed each pass
__device__ unsigned gcnt[B];
__device__ u64      gkey[B][CCAP];
__device__ unsigned grank[B][CCAP];       // zeroed in P1 each pass
__device__ float    gssc[B][KTOP];
__device__ unsigned gslab[B][KTOP];
__device__ unsigned gcp[B][KTOP];         // (class<<16)|pos
__device__ float4   gsbox[B][KTOP];
__device__ float    gsx1[B][KTOP], gsy1[B][KTOP], gsx2[B][KTOP],
                    gsy2[B][KTOP], gsar[B][KTOP];
__device__ unsigned gclsflat[B][ROWS];    // flat row -> global rank
__device__ unsigned gmeta[B][12];         // base[4], ncls[4], nval[4]
__device__ __align__(16) unsigned gmat[B][ROWS][32];
__device__ __align__(16) unsigned gdiag[B][ROWS];
__device__ unsigned gnzrow[B][ROWS];      // zeroed each pass (holes must be 0)
__device__ unsigned gbarc[B][8];          // per-batch epoch barrier counters

// Exact sigmoid: float exp via double exp (correctly rounded to float =>
// matches faithful libm expf), then float add + div as XLA expands logistic.
__device__ __forceinline__ float sigx(float x) {
    float t = (float)exp(-(double)x);
    return __fdiv_rn(1.0f, __fadd_rn(1.0f, t));
}
// Fast approximate sigmoid — superset selection only.
__device__ __forceinline__ float siga(float x) {
    return __fdividef(1.0f, 1.0f + __expf(-x));
}
// per-batch barrier (8 CTAs), epoch-based, graph-replay safe
__device__ __forceinline__ void bbarrier(int b, int k) {
    __syncthreads();
    if (threadIdx.x == 0) {
        __threadfence();
        unsigned old   = atomicAdd(&gbarc[b][k], 1u);
        unsigned epoch = old >> 3;
        volatile unsigned* p = &gbarc[b][k];
        unsigned target = (epoch + 1u) << 3;
        while (*p < target) { }
        __threadfence();
    }
    __syncthreads();
}
// guarded warp suffix-sum (inclusive from high lanes)
__device__ __forceinline__ unsigned suffix_sum(unsigned v, int lane) {
#pragma unroll
    for (int o = 1; o < 32; o <<= 1) {
        unsigned t = __shfl_down_sync(FULL, v, o);
        if (lane + o < 32) v += t;
    }
    return v;
}

#define SMEM_TOTAL 33024
extern __shared__ unsigned char smem_raw[];

__global__ void __launch_bounds__(NT, 1)
fcos_persist(const float* __restrict__ cls, const float* __restrict__ ctr,
             const float* __restrict__ reg, const float* __restrict__ coords,
             const float* __restrict__ pstr, float* __restrict__ out)
{
    const int cta  = blockIdx.x;
    const int b    = cta >> 3;
    const int r    = cta & 7;
    const int tid  = threadIdx.x;
    const int lane = tid & 31;
    const int wid  = tid >> 5;

    __shared__ unsigned chunk[1024];
    __shared__ unsigned supr[32];
    __shared__ float redmax[32], redmin[32];
    __shared__ float s_mx, s_mn;
    __shared__ unsigned s_thr;
    __shared__ unsigned soff[32][4], swcnt[32][4], swv[32][4];
    __shared__ unsigned smeta[12];          // base[4], ncls[4], nval[4]
    __shared__ unsigned snzw[(ROWS + 31) / 32];
    __shared__ unsigned srem4[4][32];

    const float4* clsB = (const float4*)cls + (size_t)b * NA;
    const float*  ctrB = ctr + (size_t)b * NA;

    // ============ P1: zero scratch + approx-score histogram ================
    if (r == 0 && tid == 0) gcnt[b] = 0;
    if (tid < 512) grank[b][r * 512 + tid] = 0u;
    for (int i = r * NT + tid; i < NA; i += 8 * NT) {
        float4 c = clsB[i];
        float m = fmaxf(fmaxf(c.x, c.y), fmaxf(c.z, c.w));   // sigmoid monotone
        float score = __fsqrt_rn(siga(m) * siga(ctrB[i]));
        atomicAdd(&ghist[b][__float_as_uint(score) >> 16], 1u);
    }
    bbarrier(b, 0);

    // ============ P2: threshold (warp-parallel suffix scans) ================
    { unsigned s = 0; int base = tid * 16;
#pragma unroll
      for (int q = 0; q < 16; ++q) s += ghist[b][base + q];
      chunk[tid] = s; }
    __syncthreads();
    { unsigned s = chunk[wid * 32 + lane];
#pragma unroll
      for (int o = 16; o; o >>= 1) s += __shfl_xor_sync(FULL, s, o);
      if (lane == 0) supr[wid] = s; }
    __syncthreads();
    if (wid == 0) {
        unsigned suf = suffix_sum(supr[lane], lane);
        unsigned m1  = __ballot_sync(FULL, suf >= KTOP);
        int sblk     = 31 - __clz(m1);
        unsigned above = (sblk < 31) ? __shfl_sync(FULL, suf, sblk + 1) : 0u;
        unsigned cs  = suffix_sum(chunk[sblk * 32 + lane], lane);
        unsigned m2  = __ballot_sync(FULL, cs + above >= KTOP);
        int cc       = 31 - __clz(m2);
        unsigned above2 = above + ((cc < 31) ? __shfl_sync(FULL, cs, cc + 1) : 0u);
        int binbase  = (sblk * 32 + cc) * 16;
        unsigned bs  = suffix_sum((lane < 16) ? ghist[b][binbase + lane] : 0u, lane);
        unsigned m3  = __ballot_sync(FULL, bs + above2 >= KTOP);
        int bb       = 31 - __clz(m3);
        if (lane == 0) {
            int T = binbase + bb;
            s_thr = (T > 0) ? (unsigned)(T - 1) : 0u;   // one-bin superset margin
        }
    }
    __syncthreads();
    const unsigned T = s_thr;

    // ============ P2b: fused compact + exact rescore ========================
    for (int i = r * NT + tid; i < NA; i += 8 * NT) {
        float4 c = clsB[i];
        float xs0 = c.x, xs1 = c.y, xs2 = c.z, xs3 = c.w;
        float m = fmaxf(fmaxf(xs0, xs1), fmaxf(xs2, xs3));
        float ctrv = ctrB[i];
        float sa = __fsqrt_rn(siga(m) * siga(ctrv));
        if ((__float_as_uint(sa) >> 16) >= T) {
            unsigned p = atomicAdd(&gcnt[b], 1u);
            if (p < CCAP) {
                int im = 0; float mm = xs0;
                if (xs1 > mm) { mm = xs1; im = 1; }
                if (xs2 > mm) { mm = xs2; im = 2; }
                if (xs3 > mm) { mm = xs3; im = 3; }
                float sm = sigx(mm);                    // == max of 4 sigmoids
                int lab = im;
                if (im > 0) {                           // first-argmax tie guard
                    float lim = mm - 1e-4f;
                    if (xs0 > lim || (im > 1 && xs1 > lim) || (im > 2 && xs2 > lim)) {
                        if (xs0 > lim && sigx(xs0) == sm) lab = 0;
                        else if (im > 1 && xs1 > lim && sigx(xs1) == sm) lab = 1;
                        else if (im > 2 && xs2 > lim && sigx(xs2) == sm) lab = 2;
                    }
                }
                float sctr  = sigx(ctrv);
                float score = __fsqrt_rn(__fmul_rn(sm, sctr));
                gkey[b][p] = ((u64)__float_as_uint(score) << 32)
                           | ((u64)(0x7FFFu - (unsigned)i) << 4) | (u64)(lab + 1);
            }
        }
    }
    bbarrier(b, 1);

    int C = (int)gcnt[b]; if (C > CCAP) C = CCAP;

    // ============ P3: brute-force rank (8 CTAs, O(C^2)/8 each) ==============
    {
        u64* skeys = (u64*)smem_raw;
        for (int i = tid; i < C; i += NT) skeys[i] = gkey[b][i];
        __syncthreads();
        int j0 = (r * C) >> 3, j1 = ((r + 1) * C) >> 3;
        for (int i = tid; i < C; i += NT) {
            u64 ki = skeys[i];
            unsigned cnt = 0;
#pragma unroll 8
            for (int j = j0; j < j1; ++j) cnt += (skeys[j] > ki) ? 1u : 0u;
            if (cnt) atomicAdd(&grank[b][i], cnt);
        }
    }
    bbarrier(b, 2);

    // ============ P4: r==0 gather + boxes + class compaction; r>0 zero ======
    if (r == 0) {
        u64* skey = (u64*)smem_raw;             // KTOP u64
        for (int i = tid; i < C; i += NT) {
            unsigned rk = grank[b][i];
            if (rk < KTOP) skey[rk] = gkey[b][i];
        }
        __syncthreads();

        float x1 = 0, y1 = 0, x2 = 0, y2 = 0, score = 0;
        int label = 0; bool validf = false;
        if (tid < KTOP) {
            u64 key = skey[tid];
            score  = __uint_as_float((unsigned)(key >> 32));
            label  = (int)(key & 0xFull);
            int idx = 0x7FFF - (int)((key >> 4) & 0x7FFFull);
            validf = (score >= 0.05f);

            float4 r4 = ((const float4*)reg)[(size_t)b * NA + idx];
            float2 xy = ((const float2*)coords)[idx];
            float  st = pstr[idx];
            x1 = __fsub_rn(xy.x, __fmul_rn(r4.x, st));
            y1 = __fsub_rn(xy.y, __fmul_rn(r4.y, st));
            x2 = __fadd_rn(xy.x, __fmul_rn(r4.z, st));
            y2 = __fadd_rn(xy.y, __fmul_rn(r4.w, st));
            x1 = fminf(fmaxf(x1, 0.0f), 1023.0f);
            y1 = fminf(fmaxf(y1, 0.0f), 799.0f);
            x2 = fminf(fmaxf(x2, 0.0f), 1023.0f);
            y2 = fminf(fmaxf(y2, 0.0f), 799.0f);

            gsbox[b][tid] = make_float4(x1, y1, x2, y2);
            gssc[b][tid]  = score;
            gslab[b][tid] = (unsigned)label;
        }

        // class ballots (labels 1..4 -> c 0..3)
        int myc = (tid < KTOP) ? (label - 1) : -1;
        unsigned mybal = 0;
#pragma unroll
        for (int cc2 = 0; cc2 < 4; ++cc2) {
            unsigned bal  = __ballot_sync(FULL, myc == cc2);
            unsigned balv = __ballot_sync(FULL, myc == cc2 && validf);
            if (lane == 0) { swcnt[wid][cc2] = __popc(bal); swv[wid][cc2] = __popc(balv); }
            if (myc == cc2) mybal = bal;
        }

        // mx/mn reduction
        float vmax = -1000000000.0f, vmin = 1000000000.0f;
        if (tid < KTOP && validf) {
            vmax = fmaxf(fmaxf(x1, y1), fmaxf(x2, y2));
            vmin = fminf(fminf(x1, y1), fminf(x2, y2));
        }
#pragma unroll
        for (int o = 16; o; o >>= 1) {
            vmax = fmaxf(vmax, __shfl_xor_sync(FULL, vmax, o));
            vmin = fminf(vmin, __shfl_xor_sync(FULL, vmin, o));
        }
        if (lane == 0) { redmax[wid] = vmax; redmin[wid] = vmin; }
        __syncthreads();
        if (tid == 0) {
            float mx = redmax[0], mn = redmin[0];
            for (int w = 1; w < 32; ++w) { mx = fmaxf(mx, redmax[w]); mn = fminf(mn, redmin[w]); }
            s_mx = mx; s_mn = mn;
            unsigned run[4] = {0,0,0,0}, nvv[4] = {0,0,0,0};
            for (int w = 0; w < 32; ++w)
#pragma unroll
                for (int cc2 = 0; cc2 < 4; ++cc2) {
                    soff[w][cc2] = run[cc2];
                    run[cc2] += swcnt[w][cc2];
                    nvv[cc2]  += swv[w][cc2];
                }
            unsigned base = 0;
#pragma unroll
            for (int cc2 = 0; cc2 < 4; ++cc2) {
                smeta[cc2]     = base;          // base (32-aligned)
                smeta[4 + cc2] = run[cc2];      // ncls
                smeta[8 + cc2] = nvv[cc2];      // nval
                base = (base + run[cc2] + 31u) & ~31u;
            }
            for (int q2 = 0; q2 < 12; ++q2) gmeta[b][q2] = smeta[q2];
        }
        __syncthreads();

        if (tid < KTOP) {
            float off = __fmul_rn((float)label, __fadd_rn(__fsub_rn(s_mx, s_mn), 1.0f));
            float a  = __fadd_rn(x1, off), bb = __fadd_rn(y1, off);
            float cc3 = __fadd_rn(x2, off), dd = __fadd_rn(y2, off);
            gsx1[b][tid] = a;  gsy1[b][tid] = bb;
            gsx2[b][tid] = cc3; gsy2[b][tid] = dd;
            gsar[b][tid] = __fmul_rn(__fsub_rn(cc3, a), __fsub_rn(dd, bb));
            unsigned pos = soff[wid][myc] + __popc(mybal & ((1u << lane) - 1u));
            unsigned fr  = smeta[myc] + pos;
            gclsflat[b][fr] = (unsigned)tid;
            gcp[b][tid] = ((unsigned)myc << 16) | pos;
        }
    } else {
        int z0 = (r - 1) * 2341, z1 = (r == 7) ? NBINS : z0 + 2341;
        for (int i = z0 + tid; i < z1; i += NT) ghist[b][i] = 0;
        if (r == 1) for (int i = tid; i < ROWS; i += NT) gnzrow[b][i] = 0u;
    }
    bbarrier(b, 3);

    // ============ P5: per-class bit-matrix (all 8 CTAs) =====================
    {
        float* sx1 = (float*)smem_raw;
        float* sy1 = sx1 + KTOP; float* sx2 = sy1 + KTOP;
        float* sy2 = sx2 + KTOP; float* sar = sy2 + KTOP;
        unsigned* sflat = (unsigned*)(sar + KTOP);     // ROWS entries
        for (int j = tid; j < KTOP; j += NT) {
            sx1[j] = gsx1[b][j]; sy1[j] = gsy1[b][j];
            sx2[j] = gsx2[b][j]; sy2[j] = gsy2[b][j];
            sar[j] = gsar[b][j];
        }
        for (int j = tid; j < ROWS; j += NT) sflat[j] = gclsflat[b][j];
        if (tid < 12) smeta[tid] = gmeta[b][tid];
        __syncthreads();

        unsigned b1 = smeta[1], b2 = smeta[2], b3 = smeta[3];
        for (int k = wid; k < ROWS / 8; k += 32) {
            int fr = r + 8 * k;
            int c = (fr >= (int)b1) + (fr >= (int)b2) + (fr >= (int)b3);
            int base = (int)smeta[c];
            int nc   = (int)smeta[4 + c];
            int pos  = fr - base;
            if (pos >= nc) continue;                    // hole (uniform per warp)
            int gi = (int)sflat[fr];
            float ax1 = sx1[gi], ay1 = sy1[gi], ax2 = sx2[gi], ay2 = sy2[gi], aa = sar[gi];
            unsigned myword = 0;
            int nw  = (nc + 31) >> 5;
            int jc0 = (pos + 1) >> 5;
            for (int jc = jc0; jc < nw; ++jc) {
                int jpos = jc * 32 + lane;
                bool sup = false;
                if (jpos > pos && jpos < nc) {
                    int gj = (int)sflat[base + jpos];
                    float ix1 = fmaxf(ax1, sx1[gj]);
                    float iy1 = fmaxf(ay1, sy1[gj]);
                    float ix2 = fminf(ax2, sx2[gj]);
                    float iy2 = fminf(ay2, sy2[gj]);
                    float iw  = fmaxf(__fsub_rn(ix2, ix1), 0.0f);
                    float ih  = fmaxf(__fsub_rn(iy2, iy1), 0.0f);
                    float inter = __fmul_rn(iw, ih);
                    float uni = fmaxf(__fsub_rn(__fadd_rn(aa, sar[gj]), inter), 1e-9f);
                    sup = __fdiv_rn(inter, uni) > 0.5f;
                }
                unsigned wbits = __ballot_sync(FULL, sup);
                if (lane == jc) myword = wbits;
            }
            gmat[b][fr][lane] = myword;
            if (lane == (pos >> 5)) gdiag[b][fr] = myword;
            unsigned any = __ballot_sync(FULL, myword != 0u);
            if (lane == 0) gnzrow[b][fr] = any ? 1u : 0u;
        }
    }
    bbarrier(b, 4);

    // ============ P6: 4-class parallel block-serial NMS + outputs (r==0) ====
    if (r != 0) return;
    {
        unsigned* sdiag = (unsigned*)smem_raw;          // ROWS u32
        // padded loop: every warp fully active at each ballot (ROWS=1104 < 2*NT)
#pragma unroll
        for (int t2 = 0; t2 < 2; ++t2) {
            int i = t2 * NT + tid;
            bool inr = (i < ROWS);
            unsigned v = inr ? gnzrow[b][i] : 0u;
            unsigned bal = __ballot_sync(FULL, v != 0u);
            if (inr) {
                sdiag[i] = gdiag[b][i];
                if ((i & 31) == 0) snzw[i >> 5] = bal;
            }
        }
        if (tid < 12) smeta[tid] = gmeta[b][tid];
        __syncthreads();

        if (wid < 4) {
            const int c    = wid;
            const int base = (int)smeta[c];
            const int nval = (int)smeta[8 + c];
            const int fbw  = base >> 5;                 // base is 32-aligned
            unsigned rm;
            int lo = 32 * lane;
            if (lo >= nval) rm = FULL;
            else if (lo + 32 <= nval) rm = 0u;
            else rm = FULL << (nval - lo);
            unsigned removed = rm;

            int nbk = (nval + 31) >> 5;
            for (int bk = 0; bk < nbk; ++bk) {
                unsigned curw = __shfl_sync(FULL, removed, bk);
                unsigned kept = 0;
                if (lane == 0) {
                    const uint4* dg = (const uint4*)(sdiag + (fbw + bk) * 32);
                    uint4 v0 = dg[0], v1 = dg[1], v2 = dg[2], v3 = dg[3];
                    uint4 v4 = dg[4], v5 = dg[5], v6 = dg[6], v7 = dg[7];
                    unsigned anyd = (v0.x|v0.y|v0.z|v0.w)|(v1.x|v1.y|v1.z|v1.w)
                                  | (v2.x|v2.y|v2.z|v2.w)|(v3.x|v3.y|v3.z|v3.w)
                                  | (v4.x|v4.y|v4.z|v4.w)|(v5.x|v5.y|v5.z|v5.w)
                                  | (v6.x|v6.y|v6.z|v6.w)|(v7.x|v7.y|v7.z|v7.w);
                    if (anyd == 0u) {
                        kept = ~curw;
                    } else {
                        unsigned rem = curw;
                        const uint4 vv[8] = {v0,v1,v2,v3,v4,v5,v6,v7};
#pragma unroll
                        for (int q = 0; q < 8; ++q) {
                            int j0 = q * 4;
                            if (!((rem >> (j0+0)) & 1u)) { kept |= 1u << (j0+0); rem |= vv[q].x; }
                            if (!((rem >> (j0+1)) & 1u)) { kept |= 1u << (j0+1); rem |= vv[q].y; }
                            if (!((rem >> (j0+2)) & 1u)) { kept |= 1u << (j0+2); rem |= vv[q].z; }
                            if (!((rem >> (j0+3)) & 1u)) { kept |= 1u << (j0+3); rem |= vv[q].w; }
                        }
                    }
                }
                kept = __shfl_sync(FULL, kept, 0);
                unsigned todo = kept & snzw[fbw + bk];
                while (todo) {                           // warp-uniform sparse ORs
                    int j = __ffs(todo) - 1; todo &= todo - 1;
                    removed |= gmat[b][(fbw + bk) * 32 + j][lane];
                }
            }
            srem4[c][lane] = removed;
        }
        __syncthreads();

        if (tid < KTOP) {
            unsigned cp = gcp[b][tid];
            unsigned c = cp >> 16, pos = cp & 0xFFFFu;
            bool k = ((srem4[c][pos >> 5] >> (pos & 31)) & 1u) == 0u;
            float so = k ? gssc[b][tid] : 0.0f;
            float lo2 = k ? (float)gslab[b][tid] : 0.0f;
            float4 bx = gsbox[b][tid];
            if (!k) bx = make_float4(0.f, 0.f, 0.f, 0.f);
            out[(size_t)b * KTOP + tid] = so;
            out[(size_t)(B * KTOP) + (size_t)b * KTOP + tid] = lo2;
            size_t obase = (size_t)(2 * B * KTOP) + ((size_t)b * KTOP + tid) * 4;
            out[obase + 0] = bx.x; out[obase + 1] = bx.y;
            out[obase + 2] = bx.z; out[obase + 3] = bx.w;
        }
    }
}

extern "C" void kernel_launch(void* const* d_in, const int* in_sizes, int n_in,
                              void* d_out, int out_size) {
    (void)in_sizes; (void)n_in; (void)out_size;
    static bool attr_done = false;
    if (!attr_done) {
        cudaFuncSetAttribute(fcos_persist, cudaFuncAttributeMaxDynamicSharedMemorySize,
                             SMEM_TOTAL);
        attr_done = true;
    }
    fcos_persist<<<NCTA, NT, SMEM_TOTAL>>>(
        (const float*)d_in[0], (const float*)d_in[1], (const float*)d_in[2],
        (const float*)d_in[3], (const float*)d_in[4], (float*)d_out);
}